// round 2
// baseline (speedup 1.0000x reference)
#include <cuda_runtime.h>

// ---------------- scratch (device globals; no allocation allowed) ----------------
__device__ float g_h1[(size_t)32*64*128*128];   // enc1 out, NCHW
__device__ float g_h2[(size_t)32*64*64*32];     // enc2 out, NHWC [img][y][x][c]
__device__ int   g_idx[131072];                 // VQ indices
__device__ float g_d1[(size_t)32*32*64*64];     // dec1 out, NCHW
__device__ float g_d2[(size_t)32*64*128*128];   // dec2 out, NCHW
__device__ float g_loss;

// ---------------- zero loss accumulator ----------------
__global__ void k_zero() { g_loss = 0.f; }

// ---------------- enc1: 3->64, 3x3 s2 p1, ReLU ----------------
// grid 1024 (32 img x 32 tiles), 256 thr. Out tile 32w x 16h, 2 rows/thread.
__global__ __launch_bounds__(256) void k_enc1(const float* __restrict__ x,
                                              const float* __restrict__ w,
                                              const float* __restrict__ bias)
{
    __shared__ float sIn[3*33*65];
    __shared__ float sW[64*27];
    __shared__ float sB[64];
    int blk = blockIdx.x;
    int img = blk >> 5;
    int tile = blk & 31;
    int tx0 = (tile & 3) * 32;
    int ty0 = (tile >> 2) * 16;
    int tid = threadIdx.x;
    for (int i = tid; i < 64*27; i += 256) sW[i] = w[i];
    if (tid < 64) sB[tid] = bias[tid];
    int iy0 = 2*ty0 - 1, ix0 = 2*tx0 - 1;
    const float* xim = x + (size_t)img*3*65536;
    for (int i = tid; i < 3*33*65; i += 256) {
        int c = i / (33*65); int rem = i - c*(33*65);
        int r = rem / 65; int cc = rem - r*65;
        int gy = iy0 + r, gx = ix0 + cc;
        float v = 0.f;
        if (gy >= 0 && gy < 256 && gx >= 0 && gx < 256)
            v = xim[(size_t)c*65536 + gy*256 + gx];
        sIn[i] = v;
    }
    __syncthreads();
    int tx = tid & 31, tyq = tid >> 5;   // 32 x 8
    float in[3][5][3];
    int lr0 = 4*tyq, lc0 = 2*tx;
    #pragma unroll
    for (int c = 0; c < 3; c++)
        #pragma unroll
        for (int r = 0; r < 5; r++)
            #pragma unroll
            for (int cc = 0; cc < 3; cc++)
                in[c][r][cc] = sIn[c*(33*65) + (lr0+r)*65 + lc0+cc];
    float* h1o = g_h1 + (size_t)img*64*16384;
    int oy = ty0 + 2*tyq, ox = tx0 + tx;
    #pragma unroll 1
    for (int ocg = 0; ocg < 64; ocg += 8) {
        float a0[8], a1[8];
        #pragma unroll
        for (int o = 0; o < 8; o++) { a0[o] = sB[ocg+o]; a1[o] = a0[o]; }
        #pragma unroll
        for (int c = 0; c < 3; c++)
            #pragma unroll
            for (int ky = 0; ky < 3; ky++)
                #pragma unroll
                for (int kx = 0; kx < 3; kx++) {
                    float v0 = in[c][ky][kx], v1 = in[c][ky+2][kx];
                    #pragma unroll
                    for (int o = 0; o < 8; o++) {
                        float wv = sW[(ocg+o)*27 + c*9 + ky*3 + kx];
                        a0[o] = fmaf(v0, wv, a0[o]);
                        a1[o] = fmaf(v1, wv, a1[o]);
                    }
                }
        #pragma unroll
        for (int o = 0; o < 8; o++) {
            h1o[(size_t)(ocg+o)*16384 + (size_t)oy*128 + ox]     = fmaxf(a0[o], 0.f);
            h1o[(size_t)(ocg+o)*16384 + (size_t)(oy+1)*128 + ox] = fmaxf(a1[o], 0.f);
        }
    }
}

// ---------------- enc2: 64->32, 3x3 s2 p1, ReLU, out NHWC ----------------
// grid 512 = 32 img x 8 tiles x 2 ocgroups; 128 thr; thread = 2x2 out px, 16 oc.
__global__ __launch_bounds__(128) void k_enc2(const float* __restrict__ w,
                                              const float* __restrict__ bias)
{
    __shared__ float sW[16*64*9];   // 9216 floats
    __shared__ float sIn[33*65];
    __shared__ float sB[16];
    int b = blockIdx.x;
    int og = b & 1;
    int t = (b >> 1) & 7;
    int img = b >> 4;
    int ox0 = (t & 1) * 32;
    int oy0 = (t >> 1) * 16;
    int tid = threadIdx.x;
    for (int i = tid; i < 9216; i += 128) sW[i] = w[og*9216 + i];
    if (tid < 16) sB[tid] = bias[og*16 + tid];
    __syncthreads();
    int ttx = tid & 15, tty = tid >> 4;  // 16 x 8
    float acc[2][2][16];
    #pragma unroll
    for (int r = 0; r < 2; r++)
        #pragma unroll
        for (int cc = 0; cc < 2; cc++)
            #pragma unroll
            for (int o = 0; o < 16; o++) acc[r][cc][o] = sB[o];
    const float* h1im = g_h1 + (size_t)img*64*16384;
    int iy0 = 2*oy0 - 1, ix0 = 2*ox0 - 1;
    #pragma unroll 1
    for (int cin = 0; cin < 64; cin++) {
        const float* hp = h1im + (size_t)cin*16384;
        __syncthreads();
        for (int i = tid; i < 33*65; i += 128) {
            int r = i / 65, cc = i - r*65;
            int gy = iy0 + r, gx = ix0 + cc;
            float v = 0.f;
            if (gy >= 0 && gy < 128 && gx >= 0 && gx < 128)
                v = hp[gy*128 + gx];
            sIn[i] = v;
        }
        __syncthreads();
        float in[5][5];
        #pragma unroll
        for (int r = 0; r < 5; r++)
            #pragma unroll
            for (int c = 0; c < 5; c++)
                in[r][c] = sIn[(4*tty + r)*65 + 4*ttx + c];
        #pragma unroll
        for (int ky = 0; ky < 3; ky++)
            #pragma unroll
            for (int kx = 0; kx < 3; kx++)
                #pragma unroll
                for (int o = 0; o < 16; o++) {
                    float wv = sW[o*576 + cin*9 + ky*3 + kx];
                    #pragma unroll
                    for (int r = 0; r < 2; r++)
                        #pragma unroll
                        for (int cc = 0; cc < 2; cc++)
                            acc[r][cc][o] = fmaf(in[2*r+ky][2*cc+kx], wv, acc[r][cc][o]);
                }
    }
    #pragma unroll
    for (int r = 0; r < 2; r++)
        #pragma unroll
        for (int cc = 0; cc < 2; cc++) {
            int oy = oy0 + 2*tty + r, ox = ox0 + 2*ttx + cc;
            float* dp = g_h2 + ((size_t)(img*64 + oy)*64 + ox)*32 + og*16;
            #pragma unroll
            for (int o = 0; o < 16; o++) dp[o] = fmaxf(acc[r][cc][o], 0.f);
        }
}

// ---------------- enc3 (1x1, 32->64) + VQ argmin + loss ----------------
// grid 512 x 256 thr = 131072 pixels, 1 px/thread, codebook in dyn smem.
__global__ __launch_bounds__(256) void k_enc3_vq(const float* __restrict__ w3,
                                                 const float* __restrict__ b3,
                                                 const float* __restrict__ cb)
{
    extern __shared__ float sm[];
    float* sCB = sm;            // 32768
    float* sCn = sm + 32768;    // 512
    float* sW  = sm + 33280;    // 2048
    float* sB  = sm + 35328;    // 64
    int tid = threadIdx.x;
    for (int i = tid; i < 32768; i += 256) sCB[i] = cb[i];
    for (int i = tid; i < 2048; i += 256) sW[i] = w3[i];
    if (tid < 64) sB[tid] = b3[tid];
    __syncthreads();
    for (int k = tid; k < 512; k += 256) {
        float s = 0.f;
        #pragma unroll 8
        for (int d = 0; d < 64; d++) { float v = sCB[k*64+d]; s = fmaf(v, v, s); }
        sCn[k] = s;
    }
    __syncthreads();
    int p = blockIdx.x*256 + tid;
    const float4* hp = reinterpret_cast<const float4*>(g_h2 + (size_t)p*32);
    float h[32];
    #pragma unroll
    for (int q = 0; q < 8; q++) {
        float4 v = hp[q];
        h[4*q] = v.x; h[4*q+1] = v.y; h[4*q+2] = v.z; h[4*q+3] = v.w;
    }
    // z = W3 @ h + b3
    float z[64];
    const float4* sW4 = reinterpret_cast<const float4*>(sW);
    #pragma unroll
    for (int d = 0; d < 64; d++) {
        float a0 = 0.f, a1 = 0.f, a2 = 0.f, a3 = 0.f;
        #pragma unroll
        for (int q = 0; q < 8; q++) {
            float4 wv = sW4[d*8 + q];
            a0 = fmaf(wv.x, h[4*q],   a0);
            a1 = fmaf(wv.y, h[4*q+1], a1);
            a2 = fmaf(wv.z, h[4*q+2], a2);
            a3 = fmaf(wv.w, h[4*q+3], a3);
        }
        z[d] = sB[d] + ((a0+a1) + (a2+a3));
    }
    // argmin_k  cnorm[k] - 2 z.c_k  (||z||^2 constant, dropped)
    const float4* sCB4 = reinterpret_cast<const float4*>(sCB);
    float bestd = 3.4e38f;
    int besti = 0;
    #pragma unroll 2
    for (int k = 0; k < 512; k++) {
        const float4* ck = sCB4 + k*16;
        float d0 = 0.f, d1 = 0.f, d2 = 0.f, d3 = 0.f;
        #pragma unroll
        for (int q = 0; q < 16; q++) {
            float4 cv = ck[q];
            d0 = fmaf(z[4*q],   cv.x, d0);
            d1 = fmaf(z[4*q+1], cv.y, d1);
            d2 = fmaf(z[4*q+2], cv.z, d2);
            d3 = fmaf(z[4*q+3], cv.w, d3);
        }
        float score = sCn[k] - 2.f*((d0+d1) + (d2+d3));
        if (score < bestd) { bestd = score; besti = k; }
    }
    g_idx[p] = besti;
    float s = 0.f;
    const float4* cbv = sCB4 + besti*16;
    #pragma unroll
    for (int q = 0; q < 16; q++) {
        float4 cv = cbv[q];
        float t0 = cv.x - z[4*q];   s = fmaf(t0, t0, s);
        float t1 = cv.y - z[4*q+1]; s = fmaf(t1, t1, s);
        float t2 = cv.z - z[4*q+2]; s = fmaf(t2, t2, s);
        float t3 = cv.w - z[4*q+3]; s = fmaf(t3, t3, s);
    }
    #pragma unroll
    for (int off = 16; off > 0; off >>= 1)
        s += __shfl_down_sync(0xffffffffu, s, off);
    if ((tid & 31) == 0) atomicAdd(&g_loss, s);
}

// ---------------- finalize losses ----------------
__global__ void k_loss_out(float* __restrict__ out)
{
    float v = g_loss * (1.f/8388608.f);   // / (131072 * 64)
    out[0] = v;   // codebook loss (forward-identical)
    out[1] = v;   // commitment loss
}

// ---------------- dec1: zq = codebook[idx]; 1x1 conv 64->32, ReLU, NCHW ----
__global__ __launch_bounds__(256) void k_dec1(const float* __restrict__ cb,
                                              const float* __restrict__ w,
                                              const float* __restrict__ bias)
{
    __shared__ float sW[32*64];
    __shared__ float sB[32];
    int tid = threadIdx.x;
    for (int i = tid; i < 2048; i += 256) sW[i] = w[i];
    if (tid < 32) sB[tid] = bias[tid];
    __syncthreads();
    int p = blockIdx.x*256 + tid;
    int ki = g_idx[p];
    float c[64];
    const float4* cp = reinterpret_cast<const float4*>(cb + (size_t)ki*64);
    #pragma unroll
    for (int q = 0; q < 16; q++) {
        float4 v = cp[q];
        c[4*q] = v.x; c[4*q+1] = v.y; c[4*q+2] = v.z; c[4*q+3] = v.w;
    }
    int img = p >> 12;
    int rem = p & 4095;
    float* dp = g_d1 + (size_t)img*32*4096 + rem;
    const float4* sW4 = reinterpret_cast<const float4*>(sW);
    #pragma unroll 1
    for (int oc = 0; oc < 32; oc++) {
        float a0 = 0.f, a1 = 0.f, a2 = 0.f, a3 = 0.f;
        #pragma unroll
        for (int q = 0; q < 16; q++) {
            float4 wv = sW4[oc*16 + q];
            a0 = fmaf(wv.x, c[4*q],   a0);
            a1 = fmaf(wv.y, c[4*q+1], a1);
            a2 = fmaf(wv.z, c[4*q+2], a2);
            a3 = fmaf(wv.w, c[4*q+3], a3);
        }
        float v = sB[oc] + ((a0+a1) + (a2+a3));
        dp[(size_t)oc*4096] = fmaxf(v, 0.f);
    }
}

// ---------------- fused bilinear up2x + 3x3 conv p1 ----------------
// Out tile 32w x 16h, 128 thr (16x8), 2x2 px/thread, OCG out channels/block.
template<int CIN, int S, int COUT, int OCG, bool RELU>
__global__ __launch_bounds__(128) void k_upconv(const float* __restrict__ w,
                                                const float* __restrict__ bias,
                                                float* __restrict__ dst_ext)
{
    constexpr int NOG = COUT/OCG;
    constexpr int TXS = (2*S)/32;
    constexpr int TYS = (2*S)/16;
    __shared__ float sW[OCG*CIN*9];
    __shared__ float sB[OCG];
    __shared__ float sD[10*18];
    __shared__ float sU[18*34];
    const float* src = (CIN == 32) ? (const float*)g_d1 : (const float*)g_d2;
    float* dst = (COUT == 64) ? (float*)g_d2 : dst_ext;
    int b = blockIdx.x;
    int og = b % NOG;
    int t = b / NOG;
    int txt = t % TXS;
    int tyt = (t/TXS) % TYS;
    int img = t/(TXS*TYS);
    int tid = threadIdx.x;
    for (int i = tid; i < OCG*CIN*9; i += 128) sW[i] = w[og*OCG*CIN*9 + i];
    if (tid < OCG) sB[tid] = bias[og*OCG + tid];
    __syncthreads();
    int ttx = tid & 15, tty = tid >> 4;
    float acc[2][2][OCG];
    #pragma unroll
    for (int r = 0; r < 2; r++)
        #pragma unroll
        for (int cc = 0; cc < 2; cc++)
            #pragma unroll
            for (int o = 0; o < OCG; o++) acc[r][cc][o] = sB[o];
    int ry0 = 8*tyt - 1, rx0 = 16*txt - 1;
    const float* simg = src + (size_t)img*CIN*S*S;
    #pragma unroll 1
    for (int cin = 0; cin < CIN; cin++) {
        const float* sp = simg + (size_t)cin*S*S;
        for (int i = tid; i < 180; i += 128) {
            int r = i/18, c = i - r*18;
            int sy = ry0 + r; sy = sy < 0 ? 0 : (sy > S-1 ? S-1 : sy);
            int sx = rx0 + c; sx = sx < 0 ? 0 : (sx > S-1 ? S-1 : sx);
            sD[i] = sp[sy*S + sx];
        }
        __syncthreads();
        for (int i = tid; i < 612; i += 128) {
            int r = i/34, c = i - r*34;
            int uy = 16*tyt - 1 + r, ux = 32*txt - 1 + c;
            float v = 0.f;
            if (uy >= 0 && uy < 2*S && ux >= 0 && ux < 2*S) {
                int ky = uy >> 1, kx = ux >> 1;
                int ay, by; float wya, wyb;
                if ((uy & 1) == 0) { ay = ky-1; by = ky;   wya = 0.25f; wyb = 0.75f; }
                else               { ay = ky;   by = ky+1; wya = 0.75f; wyb = 0.25f; }
                int ax, bx; float wxa, wxb;
                if ((ux & 1) == 0) { ax = kx-1; bx = kx;   wxa = 0.25f; wxb = 0.75f; }
                else               { ax = kx;   bx = kx+1; wxa = 0.75f; wxb = 0.25f; }
                int la = ay - ry0, lb = by - ry0, ca = ax - rx0, cb2 = bx - rx0;
                float r0 = wxa*sD[la*18 + ca] + wxb*sD[la*18 + cb2];
                float r1 = wxa*sD[lb*18 + ca] + wxb*sD[lb*18 + cb2];
                v = wya*r0 + wyb*r1;
            }
            sU[i] = v;
        }
        __syncthreads();
        float in[4][4];
        #pragma unroll
        for (int r = 0; r < 4; r++)
            #pragma unroll
            for (int c = 0; c < 4; c++)
                in[r][c] = sU[(2*tty + r)*34 + 2*ttx + c];
        #pragma unroll
        for (int ky = 0; ky < 3; ky++)
            #pragma unroll
            for (int kx = 0; kx < 3; kx++)
                #pragma unroll
                for (int o = 0; o < OCG; o++) {
                    float wv = sW[(o*CIN + cin)*9 + ky*3 + kx];
                    #pragma unroll
                    for (int r = 0; r < 2; r++)
                        #pragma unroll
                        for (int cc = 0; cc < 2; cc++)
                            acc[r][cc][o] = fmaf(in[r+ky][cc+kx], wv, acc[r][cc][o]);
                }
        __syncthreads();
    }
    #pragma unroll
    for (int r = 0; r < 2; r++)
        #pragma unroll
        for (int cc = 0; cc < 2; cc++) {
            int oy = 16*tyt + 2*tty + r, ox = 32*txt + 2*ttx + cc;
            #pragma unroll
            for (int o = 0; o < OCG; o++) {
                float v = acc[r][cc][o];
                if (RELU) v = fmaxf(v, 0.f);
                dst[((size_t)img*COUT + og*OCG + o)*(4*S*S) + (size_t)oy*(2*S) + ox] = v;
            }
        }
}

// ---------------- host launch ----------------
extern "C" void kernel_launch(void* const* d_in, const int* in_sizes, int n_in,
                              void* d_out, int out_size) {
    const float* x   = (const float*)d_in[0];
    const float* cb  = (const float*)d_in[1];
    const float* ew1 = (const float*)d_in[2];
    const float* eb1 = (const float*)d_in[3];
    const float* ew2 = (const float*)d_in[4];
    const float* eb2 = (const float*)d_in[5];
    const float* ew3 = (const float*)d_in[6];
    const float* eb3 = (const float*)d_in[7];
    const float* dw1 = (const float*)d_in[8];
    const float* db1 = (const float*)d_in[9];
    const float* dw2 = (const float*)d_in[10];
    const float* db2 = (const float*)d_in[11];
    const float* dw3 = (const float*)d_in[12];
    const float* db3 = (const float*)d_in[13];
    float* out = (float*)d_out;

    cudaFuncSetAttribute(k_enc3_vq, cudaFuncAttributeMaxDynamicSharedMemorySize, 141568);

    k_zero<<<1, 1>>>();
    k_enc1<<<1024, 256>>>(x, ew1, eb1);
    k_enc2<<<512, 128>>>(ew2, eb2);
    k_enc3_vq<<<512, 256, 141568>>>(ew3, eb3, cb);
    k_loss_out<<<1, 1>>>(out);
    k_dec1<<<512, 256>>>(cb, dw1, db1);
    k_upconv<32, 64, 64, 16, true><<<4096, 128>>>(dw2, db2, nullptr);
    k_upconv<64, 128, 3, 3, false><<<4096, 128>>>(dw3, db3, out + 2);
}